// round 1
// baseline (speedup 1.0000x reference)
#include <cuda_runtime.h>
#include <math.h>

#define N_NODES 50000
#define N_EDGES 800000
#define HDIM    256
#define NRELS   16
#define CAP     64

// ---------------- scratch (static device globals; no allocation) ------------
__device__ int   g_cnt[N_NODES];
__device__ int   g_bucket[N_NODES * CAP];
__device__ float g_red[N_NODES * HDIM];

// ---------------- kernel 1: zero per-node counters ---------------------------
__global__ void zero_cnt_kernel() {
    int i = blockIdx.x * blockDim.x + threadIdx.x;
    if (i < N_NODES) g_cnt[i] = 0;
}

// ---------------- kernel 2: bucket edges by destination ----------------------
// Packs (src | rel<<20) into one int. src < 50000 < 2^20, rel < 16.
__global__ void build_buckets_kernel(const int* __restrict__ esrc,
                                     const int* __restrict__ edst,
                                     const int* __restrict__ erel) {
    int i = blockIdx.x * blockDim.x + threadIdx.x;
    if (i >= N_EDGES) return;
    int d   = edst[i];
    int pos = atomicAdd(&g_cnt[d], 1);
    if (pos < CAP) g_bucket[d * CAP + pos] = esrc[i] | (erel[i] << 20);
}

// ---------------- kernel 3: gather-side segment reduce -----------------------
// One block per node, thread j owns h-dim j. Sums h[src][j] + relv[rel][j].
__global__ void reduce_kernel(const float* __restrict__ h,
                              const float* __restrict__ relv) {
    int node = blockIdx.x;
    int j    = threadIdx.x;

    __shared__ int s_ent[CAP];
    __shared__ int s_cnt;
    if (j == 0) {
        int c = g_cnt[node];
        s_cnt = c < CAP ? c : CAP;
    }
    __syncthreads();
    int cnt = s_cnt;
    if (j < cnt) s_ent[j] = g_bucket[node * CAP + j];
    __syncthreads();

    float acc = 0.0f;
    for (int e = 0; e < cnt; e++) {
        int en = s_ent[e];
        int s  = en & 0xFFFFF;
        int r  = en >> 20;
        acc += h[s * HDIM + j] + relv[r * HDIM + j];
    }
    g_red[node * HDIM + j] = acc;
}

// ---------------- kernel 4: fused dual-GEMM + GRU epilogue -------------------
// gi = red @ w_ih^T + b_ih ; gh = h @ w_hh^T + b_hh ; GRU gates inline.
// Block tile: BM=64 nodes x BN=32 h-dims. Per (m,j): 6 accumulators
// (gi_r, gi_z, gi_n, gh_r, gh_z, gh_n), K=256.
#define BM 64
#define BN 32
#define BK 32

__global__ __launch_bounds__(256, 2)
void gru_gemm_kernel(const float* __restrict__ h,
                     const float* __restrict__ w_ih,
                     const float* __restrict__ w_hh,
                     const float* __restrict__ b_ih,
                     const float* __restrict__ b_hh,
                     float* __restrict__ out) {
    // k-major smem tiles, +1 pad -> conflict-free transposed stores,
    // broadcast reads.
    __shared__ float sAr[BK][BM + 1];
    __shared__ float sAh[BK][BM + 1];
    __shared__ float sB[6][BK][BN + 1];

    const int t  = threadIdx.x;
    const int tx = t & 31;   // j within tile
    const int ty = t >> 5;   // m-group (0..7), each owns 8 consecutive rows
    const int m0 = blockIdx.x * BM;
    const int j0 = blockIdx.y * BN;
    const int j  = j0 + tx;

    float acc[8][6];
#pragma unroll
    for (int a = 0; a < 8; a++)
#pragma unroll
        for (int g = 0; g < 6; g++) acc[a][g] = 0.0f;

    for (int k0 = 0; k0 < HDIM; k0 += BK) {
        // ---- load A tiles (red + h), 64x32 each, transposed into smem ----
#pragma unroll
        for (int q = 0; q < 2; q++) {
            int id  = q * 256 + t;       // 0..511 float4 slots
            int ml  = id >> 3;           // 0..63 local row
            int k4  = (id & 7) * 4;      // 0,4,...,28
            int row = m0 + ml;
            float4 vr, vh;
            if (row < N_NODES) {
                vr = *(const float4*)(&g_red[row * HDIM + k0 + k4]);
                vh = *(const float4*)(&h[row * HDIM + k0 + k4]);
            } else {
                vr = make_float4(0.f, 0.f, 0.f, 0.f);
                vh = vr;
            }
            sAr[k4 + 0][ml] = vr.x; sAr[k4 + 1][ml] = vr.y;
            sAr[k4 + 2][ml] = vr.z; sAr[k4 + 3][ml] = vr.w;
            sAh[k4 + 0][ml] = vh.x; sAh[k4 + 1][ml] = vh.y;
            sAh[k4 + 2][ml] = vh.z; sAh[k4 + 3][ml] = vh.w;
        }
        // ---- load 6 weight sub-tiles (32 rows x 32 k), transposed ----
        {
            int jj = t >> 3;             // 0..31
            int k4 = (t & 7) * 4;        // 0..28
#pragma unroll
            for (int g = 0; g < 6; g++) {
                const float* W = (g < 3) ? w_ih : w_hh;
                int row = (g % 3) * 256 + j0 + jj;   // gate offset + column
                float4 v = *(const float4*)(&W[row * HDIM + k0 + k4]);
                sB[g][k4 + 0][jj] = v.x; sB[g][k4 + 1][jj] = v.y;
                sB[g][k4 + 2][jj] = v.z; sB[g][k4 + 3][jj] = v.w;
            }
        }
        __syncthreads();

        // ---- FFMA mainloop ----
#pragma unroll
        for (int k = 0; k < BK; k++) {
            float b0 = sB[0][k][tx], b1 = sB[1][k][tx], b2 = sB[2][k][tx];
            float b3 = sB[3][k][tx], b4 = sB[4][k][tx], b5 = sB[5][k][tx];
#pragma unroll
            for (int a = 0; a < 8; a++) {
                int   ml = ty * 8 + a;
                float ar = sAr[k][ml];
                float ah = sAh[k][ml];
                acc[a][0] += ar * b0;
                acc[a][1] += ar * b1;
                acc[a][2] += ar * b2;
                acc[a][3] += ah * b3;
                acc[a][4] += ah * b4;
                acc[a][5] += ah * b5;
            }
        }
        __syncthreads();
    }

    // ---- GRU epilogue ----
    float bir = b_ih[j],       biz = b_ih[j + 256], bin = b_ih[j + 512];
    float bhr = b_hh[j],       bhz = b_hh[j + 256], bhn = b_hh[j + 512];
#pragma unroll
    for (int a = 0; a < 8; a++) {
        int m = m0 + ty * 8 + a;
        if (m < N_NODES) {
            float rg = acc[a][0] + bir + acc[a][3] + bhr;
            float zg = acc[a][1] + biz + acc[a][4] + bhz;
            float r  = 1.0f / (1.0f + __expf(-rg));
            float z  = 1.0f / (1.0f + __expf(-zg));
            float n  = tanhf(acc[a][2] + bin + r * (acc[a][5] + bhn));
            float hv = h[m * HDIM + j];
            out[m * HDIM + j] = (1.0f - z) * n + z * hv;
        }
    }
}

// ---------------- launch --------------------------------------------------
extern "C" void kernel_launch(void* const* d_in, const int* in_sizes, int n_in,
                              void* d_out, int out_size) {
    const float* h    = (const float*)d_in[0];
    const float* relv = (const float*)d_in[1];
    const float* w_ih = (const float*)d_in[2];
    const float* w_hh = (const float*)d_in[3];
    const float* b_ih = (const float*)d_in[4];
    const float* b_hh = (const float*)d_in[5];
    const int*   esrc = (const int*)d_in[6];
    const int*   edst = (const int*)d_in[7];
    const int*   erel = (const int*)d_in[8];
    float*       out  = (float*)d_out;

    zero_cnt_kernel<<<(N_NODES + 255) / 256, 256>>>();
    build_buckets_kernel<<<(N_EDGES + 255) / 256, 256>>>(esrc, edst, erel);
    reduce_kernel<<<N_NODES, HDIM>>>(h, relv);

    dim3 grid((N_NODES + BM - 1) / BM, HDIM / BN);
    gru_gemm_kernel<<<grid, 256>>>(h, w_ih, w_hh, b_ih, b_hh, out);
}

// round 3
// speedup vs baseline: 1.8747x; 1.8747x over previous
#include <cuda_runtime.h>
#include <cuda_bf16.h>
#include <math.h>
#include <stdint.h>

#define N_NODES 50000
#define N_EDGES 800000
#define HDIM    256
#define CAP     64

#define MT 391          // m-tiles of 128 rows
#define JT 8            // j-tiles of 32 output dims
#define KCH 8           // k-chunks of 32
#define AC 32768        // A chunk bytes: 4 var x 128 rows x 64B
#define BC 24576        // B chunk bytes: 4 var x 96 rows x 64B

// smem layout (bytes): A stages then B stages; row stride 80B (40 bf16) ->
// conflict-free LDS for m16n8k16 fragment pattern.
#define A_STG  40960    // 4 var x 128 x 80
#define B_STG  30720    // 4 var x 96 x 80
#define B_BASE 81920
#define SMEM_TOTAL 143360

// ---------------- device scratch (static; no allocation) --------------------
__device__ int g_cnt[N_NODES];
__device__ int g_bucket[N_NODES * CAP];
__device__ __align__(16) uint8_t g_Aimg[(size_t)MT * KCH * AC]; // ~102 MB
__device__ __align__(16) uint8_t g_Bimg[(size_t)JT * KCH * BC]; // ~1.6 MB

// ---------------- PTX helpers (sm_80-level only) -----------------------------
__device__ __forceinline__ uint32_t smem_u32(const void* p) {
    uint32_t a;
    asm("{ .reg .u64 t; cvta.to.shared.u64 t, %1; cvt.u32.u64 %0, t; }"
        : "=r"(a) : "l"(p));
    return a;
}
__device__ __forceinline__ void cpasync16(uint32_t dst, const void* src) {
    asm volatile("cp.async.cg.shared.global [%0], [%1], 16;"
                 :: "r"(dst), "l"(src) : "memory");
}
#define CP_COMMIT() asm volatile("cp.async.commit_group;" ::: "memory")
#define CP_WAIT1()  asm volatile("cp.async.wait_group 1;" ::: "memory")
#define CP_WAIT0()  asm volatile("cp.async.wait_group 0;" ::: "memory")

__device__ __forceinline__ void mma_bf16(float* d, const uint32_t* a,
                                         const uint32_t* b) {
    asm volatile(
        "mma.sync.aligned.m16n8k16.row.col.f32.bf16.bf16.f32 "
        "{%0,%1,%2,%3}, {%4,%5,%6,%7}, {%8,%9}, {%0,%1,%2,%3};"
        : "+f"(d[0]), "+f"(d[1]), "+f"(d[2]), "+f"(d[3])
        : "r"(a[0]), "r"(a[1]), "r"(a[2]), "r"(a[3]), "r"(b[0]), "r"(b[1]));
}

// ---------------- kernel 1: zero counters ------------------------------------
__global__ void zero_cnt_kernel() {
    int i = blockIdx.x * blockDim.x + threadIdx.x;
    if (i < N_NODES) g_cnt[i] = 0;
}

// ---------------- kernel 2: bucket edges by destination ----------------------
__global__ void build_buckets_kernel(const int* __restrict__ esrc,
                                     const int* __restrict__ edst,
                                     const int* __restrict__ erel) {
    int i = blockIdx.x * blockDim.x + threadIdx.x;
    if (i >= N_EDGES) return;
    int d   = edst[i];
    int pos = atomicAdd(&g_cnt[d], 1);
    if (pos < CAP) g_bucket[d * CAP + pos] = esrc[i] | (erel[i] << 20);
}

// ---------------- kernel 3: segment reduce + bf16-split A-image emit ---------
// A image per (mtile,kchunk): [var4][128 rows][32 bf16]; var 0=red_hi 1=red_lo
// 2=h_hi 3=h_lo.
__global__ void reduce_convert_kernel(const float* __restrict__ h,
                                      const float* __restrict__ relv) {
    int node = blockIdx.x;
    int j    = threadIdx.x;

    __shared__ int s_ent[CAP];
    __shared__ int s_cnt;
    if (j == 0) {
        int c = g_cnt[node];
        s_cnt = c < CAP ? c : CAP;
    }
    __syncthreads();
    int cnt = s_cnt;
    if (j < cnt) s_ent[j] = g_bucket[node * CAP + j];
    __syncthreads();

    float acc = 0.0f;
    for (int e = 0; e < cnt; e++) {
        int en = s_ent[e];
        int s  = en & 0xFFFFF;
        int r  = en >> 20;
        acc += h[s * HDIM + j] + relv[r * HDIM + j];
    }

    int mtile = node >> 7, row = node & 127;
    int kc = j >> 5, kl = j & 31;
    uint8_t* cb = g_Aimg + (size_t)(mtile * KCH + kc) * AC;
    uint32_t off = (uint32_t)(row * 64 + kl * 2);

    __nv_bfloat16 rhi = __float2bfloat16(acc);
    __nv_bfloat16 rlo = __float2bfloat16(acc - __bfloat162float(rhi));
    *(__nv_bfloat16*)(cb + 0     + off) = rhi;
    *(__nv_bfloat16*)(cb + 8192  + off) = rlo;

    float hv = h[node * HDIM + j];
    __nv_bfloat16 hhi = __float2bfloat16(hv);
    __nv_bfloat16 hlo = __float2bfloat16(hv - __bfloat162float(hhi));
    *(__nv_bfloat16*)(cb + 16384 + off) = hhi;
    *(__nv_bfloat16*)(cb + 24576 + off) = hlo;
}

// ---------------- kernel 4: weight bf16-split B-image emit -------------------
// B image per (jt,kc): [var4][96 rows = gate*32+jlocal][32 bf16];
// var 0=wih_hi 1=wih_lo 2=whh_hi 3=whh_lo.
__global__ void wconv_kernel(const float* __restrict__ w_ih,
                             const float* __restrict__ w_hh) {
    int t = blockIdx.x * blockDim.x + threadIdx.x;
    if (t >= JT * KCH * 4 * 96 * 32) return;
    int kl  = t & 31;
    int r2  = t >> 5;
    int row = r2 % 96;  r2 /= 96;
    int var = r2 & 3;   r2 >>= 2;
    int kc  = r2 & 7;
    int jt  = r2 >> 3;
    int gate = row >> 5, rl = row & 31;

    const float* W = (var < 2) ? w_ih : w_hh;
    float v = W[(gate * 256 + jt * 32 + rl) * HDIM + kc * 32 + kl];
    __nv_bfloat16 hi  = __float2bfloat16(v);
    __nv_bfloat16 val = (var & 1) ? __float2bfloat16(v - __bfloat162float(hi)) : hi;

    *(__nv_bfloat16*)(g_Bimg + (size_t)(jt * KCH + kc) * BC +
                      var * 6144 + row * 64 + kl * 2) = val;
}

// ---------------- chunk loader -----------------------------------------------
__device__ __forceinline__ void load_chunk(uint32_t sb, int stage,
                                           const uint8_t* Ab,
                                           const uint8_t* Bb,
                                           int kc, int tid) {
    const uint8_t* Ag = Ab + (size_t)kc * AC;
#pragma unroll
    for (int i = 0; i < 8; i++) {           // 2048 x 16B
        int idx = tid + i * 256;
        int var = idx >> 9, row = (idx >> 2) & 127, seg = idx & 3;
        cpasync16(sb + stage * A_STG + var * 10240 + row * 80 + seg * 16,
                  Ag + var * 8192 + row * 64 + seg * 16);
    }
    const uint8_t* Bg = Bb + (size_t)kc * BC;
#pragma unroll
    for (int i = 0; i < 6; i++) {           // 1536 x 16B
        int idx = tid + i * 256;
        int var = idx / 384, row = (idx >> 2) % 96, seg = idx & 3;
        cpasync16(sb + B_BASE + stage * B_STG + var * 7680 + row * 80 + seg * 16,
                  Bg + var * 6144 + row * 64 + seg * 16);
    }
}

// ---------------- kernel 5: HMMA dual-GEMM + GRU epilogue --------------------
__global__ __launch_bounds__(256, 1)
void ggnn_mma_kernel(const float* __restrict__ h,
                     const float* __restrict__ b_ih,
                     const float* __restrict__ b_hh,
                     float* __restrict__ out) {
    extern __shared__ __align__(1024) uint8_t sm[];
    const uint32_t sb = smem_u32(sm);
    const int tid   = threadIdx.x;
    const int jtile = blockIdx.x;
    const int mtile = blockIdx.y;
    const int wid   = tid >> 5;
    const int lane  = tid & 31;
    const int lr    = lane >> 2;   // group id
    const int lc    = lane & 3;    // thread-in-group
    const int warp_m = wid & 3;    // 0..3 -> 32-row slice
    const int jhalf  = wid >> 2;   // 0..1 -> 16-dim j half

    const uint8_t* Ab = g_Aimg + (size_t)mtile * KCH * AC;
    const uint8_t* Bb = g_Bimg + (size_t)jtile * KCH * BC;

    load_chunk(sb, 0, Ab, Bb, 0, tid); CP_COMMIT();
    load_chunk(sb, 1, Ab, Bb, 1, tid); CP_COMMIT();

    // acc[mt][tile][frag]; tile = g2*6 + gate*2 + nh
    float acc[2][12][4];
#pragma unroll
    for (int a = 0; a < 2; a++)
#pragma unroll
        for (int b = 0; b < 12; b++)
#pragma unroll
            for (int c = 0; c < 4; c++) acc[a][b][c] = 0.0f;

    const int mrow = warp_m * 32;

    for (int c = 0; c < KCH; c++) {
        if (c == KCH - 1) { CP_WAIT0(); } else { CP_WAIT1(); }
        __syncthreads();
        const int s = c & 1;
        const uint32_t* As = (const uint32_t*)(sm + s * A_STG);
        const uint32_t* Bs = (const uint32_t*)(sm + B_BASE + s * B_STG);

#pragma unroll
        for (int kk = 0; kk < 2; kk++) {
            // A fragments: [var][mt][4]
            uint32_t afr[4][2][4];
#pragma unroll
            for (int var = 0; var < 4; var++)
#pragma unroll
                for (int mt = 0; mt < 2; mt++) {
                    const uint32_t* p = As + var * 2560 +
                                        (mrow + mt * 16 + lr) * 20 + kk * 8 + lc;
                    afr[var][mt][0] = p[0];
                    afr[var][mt][1] = p[160];      // +8 rows
                    afr[var][mt][2] = p[4];        // +8 k
                    afr[var][mt][3] = p[164];
                }
#pragma unroll
            for (int g2 = 0; g2 < 2; g2++)
#pragma unroll
                for (int gate = 0; gate < 3; gate++)
#pragma unroll
                    for (int nh = 0; nh < 2; nh++) {
                        const int brow = gate * 32 + jhalf * 16 + nh * 8 + lr;
                        const uint32_t* ph = Bs + (g2 * 2) * 1920 +
                                             brow * 20 + kk * 8 + lc;
                        const uint32_t* pl = ph + 1920;   // lo variant
                        uint32_t bh[2] = { ph[0], ph[4] };
                        uint32_t bl[2] = { pl[0], pl[4] };
                        const int tile = g2 * 6 + gate * 2 + nh;
#pragma unroll
                        for (int mt = 0; mt < 2; mt++) {
                            mma_bf16(acc[mt][tile], afr[2 * g2][mt], bh);
                            mma_bf16(acc[mt][tile], afr[2 * g2][mt], bl);
                            mma_bf16(acc[mt][tile], afr[2 * g2 + 1][mt], bh);
                        }
                    }
        }
        __syncthreads();
        if (c + 2 < KCH) { load_chunk(sb, s, Ab, Bb, c + 2, tid); CP_COMMIT(); }
    }

    // ---- GRU epilogue (fully register-local) ----
    const int jb = jtile * 32 + jhalf * 16;
    float Bsr[2][2], Bsz[2][2], Bin[2][2], Bhn[2][2];
#pragma unroll
    for (int nh = 0; nh < 2; nh++)
#pragma unroll
        for (int cc = 0; cc < 2; cc++) {
            int j = jb + nh * 8 + lc * 2 + cc;
            Bsr[nh][cc] = __ldg(&b_ih[j])       + __ldg(&b_hh[j]);
            Bsz[nh][cc] = __ldg(&b_ih[256 + j]) + __ldg(&b_hh[256 + j]);
            Bin[nh][cc] = __ldg(&b_ih[512 + j]);
            Bhn[nh][cc] = __ldg(&b_hh[512 + j]);
        }

#pragma unroll
    for (int mt = 0; mt < 2; mt++)
#pragma unroll
        for (int rr = 0; rr < 2; rr++) {
            int row = mtile * 128 + mrow + mt * 16 + lr + rr * 8;
            if (row >= N_NODES) continue;
#pragma unroll
            for (int nh = 0; nh < 2; nh++) {
                int j0 = jb + nh * 8 + lc * 2;
                float2 hv = *(const float2*)&h[(size_t)row * HDIM + j0];
                float o[2];
#pragma unroll
                for (int cc = 0; cc < 2; cc++) {
                    int i = rr * 2 + cc;
                    float rg = acc[mt][nh][i]     + acc[mt][6 + nh][i]  + Bsr[nh][cc];
                    float zg = acc[mt][2 + nh][i] + acc[mt][8 + nh][i]  + Bsz[nh][cc];
                    float r  = __fdividef(1.0f, 1.0f + __expf(-rg));
                    float z  = __fdividef(1.0f, 1.0f + __expf(-zg));
                    float ng = acc[mt][4 + nh][i] + Bin[nh][cc] +
                               r * (acc[mt][10 + nh][i] + Bhn[nh][cc]);
                    float ex = __expf(2.0f * ng);
                    float n  = 1.0f - __fdividef(2.0f, ex + 1.0f);
                    float hvv = (cc == 0) ? hv.x : hv.y;
                    o[cc] = (1.0f - z) * n + z * hvv;
                }
                *(float2*)&out[(size_t)row * HDIM + j0] = make_float2(o[0], o[1]);
            }
        }
}

// ---------------- launch ------------------------------------------------------
extern "C" void kernel_launch(void* const* d_in, const int* in_sizes, int n_in,
                              void* d_out, int out_size) {
    const float* h    = (const float*)d_in[0];
    const float* relv = (const float*)d_in[1];
    const float* w_ih = (const float*)d_in[2];
    const float* w_hh = (const float*)d_in[3];
    const float* b_ih = (const float*)d_in[4];
    const float* b_hh = (const float*)d_in[5];
    const int*   esrc = (const int*)d_in[6];
    const int*   edst = (const int*)d_in[7];
    const int*   erel = (const int*)d_in[8];
    float*       out  = (float*)d_out;

    cudaFuncSetAttribute(ggnn_mma_kernel,
                         cudaFuncAttributeMaxDynamicSharedMemorySize, SMEM_TOTAL);

    zero_cnt_kernel<<<(N_NODES + 255) / 256, 256>>>();
    build_buckets_kernel<<<(N_EDGES + 255) / 256, 256>>>(esrc, edst, erel);
    wconv_kernel<<<(JT * KCH * 4 * 96 * 32 + 255) / 256, 256>>>(w_ih, w_hh);
    reduce_convert_kernel<<<N_NODES, HDIM>>>(h, relv);

    dim3 grid(JT, MT);
    ggnn_mma_kernel<<<grid, 256, SMEM_TOTAL>>>(h, b_ih, b_hh, out);
}

// round 4
// speedup vs baseline: 2.5880x; 1.3805x over previous
#include <cuda_runtime.h>
#include <cuda_fp16.h>
#include <math.h>
#include <stdint.h>

#define N_NODES 50000
#define N_EDGES 800000
#define HDIM    256
#define CAP     64

#define MT 391          // m-tiles of 128 rows
#define JT 8            // j-tiles of 32 output dims
#define KCH 8           // k-chunks of 32
#define AC 32768        // A chunk: 4 var (red_hi,red_lo,h_hi,h_lo) x 128 x 64B
#define BC 12288        // B chunk: 2 var (wih,whh fp16) x 96 x 64B

// smem: A stages then B stages; row stride 80B -> conflict-free LDS.
#define A_STG  40960    // 4 var x 128 x 80
#define B_STG  15360    // 2 var x 96 x 80
#define B_BASE 81920
#define SMEM_TOTAL 112640

// ---------------- device scratch (static; no allocation) --------------------
__device__ int g_cnt[N_NODES];
__device__ int g_bucket[N_NODES * CAP];
__device__ __align__(16) uint8_t g_Aimg[(size_t)MT * KCH * AC]; // ~102 MB
__device__ __align__(16) uint8_t g_Bimg[(size_t)JT * KCH * BC]; // ~0.8 MB

// ---------------- PTX helpers (sm_80-level only) -----------------------------
__device__ __forceinline__ uint32_t smem_u32(const void* p) {
    uint32_t a;
    asm("{ .reg .u64 t; cvta.to.shared.u64 t, %1; cvt.u32.u64 %0, t; }"
        : "=r"(a) : "l"(p));
    return a;
}
__device__ __forceinline__ void cpasync16(uint32_t dst, const void* src) {
    asm volatile("cp.async.cg.shared.global [%0], [%1], 16;"
                 :: "r"(dst), "l"(src) : "memory");
}
#define CP_COMMIT() asm volatile("cp.async.commit_group;" ::: "memory")
#define CP_WAIT1()  asm volatile("cp.async.wait_group 1;" ::: "memory")
#define CP_WAIT0()  asm volatile("cp.async.wait_group 0;" ::: "memory")

__device__ __forceinline__ void mma_fp16(float* d, const uint32_t* a,
                                         const uint32_t* b) {
    asm volatile(
        "mma.sync.aligned.m16n8k16.row.col.f32.f16.f16.f32 "
        "{%0,%1,%2,%3}, {%4,%5,%6,%7}, {%8,%9}, {%0,%1,%2,%3};"
        : "+f"(d[0]), "+f"(d[1]), "+f"(d[2]), "+f"(d[3])
        : "r"(a[0]), "r"(a[1]), "r"(a[2]), "r"(a[3]), "r"(b[0]), "r"(b[1]));
}

// ---------------- kernel 1: zero counters ------------------------------------
__global__ void zero_cnt_kernel() {
    int i = blockIdx.x * blockDim.x + threadIdx.x;
    if (i < N_NODES) g_cnt[i] = 0;
}

// ---------------- kernel 2: bucket edges by destination ----------------------
__global__ void build_buckets_kernel(const int* __restrict__ esrc,
                                     const int* __restrict__ edst,
                                     const int* __restrict__ erel) {
    int i = blockIdx.x * blockDim.x + threadIdx.x;
    if (i >= N_EDGES) return;
    int d   = edst[i];
    int pos = atomicAdd(&g_cnt[d], 1);
    if (pos < CAP) g_bucket[d * CAP + pos] = esrc[i] | (erel[i] << 20);
}

// ---------------- kernel 3: segment reduce + fp16-split A-image emit ---------
// 4 nodes per block; 64 threads per node; thread owns 4 contiguous dims.
// relvector adds collapsed into a 16-bin histogram per node.
__global__ __launch_bounds__(256)
void reduce_convert_kernel(const float* __restrict__ h,
                           const float* __restrict__ relv) {
    const int grp  = threadIdx.x >> 6;             // node within block
    const int t    = threadIdx.x & 63;             // dim group
    const int node = blockIdx.x * 4 + grp;
    const int j    = t * 4;

    __shared__ int s_ent[4][CAP];
    __shared__ int s_hist[4][16];
    __shared__ int s_cnt[4];

    if (t == 0) {
        int c = g_cnt[node];
        s_cnt[grp] = c < CAP ? c : CAP;
    }
    if (t < 16) s_hist[grp][t] = 0;
    __syncthreads();

    const int cnt = s_cnt[grp];
    for (int e = t; e < cnt; e += 64) {
        int en = g_bucket[node * CAP + e];
        s_ent[grp][e] = en & 0xFFFFF;
        atomicAdd(&s_hist[grp][en >> 20], 1);
    }
    __syncthreads();

    float4 a0 = make_float4(0.f, 0.f, 0.f, 0.f);
    float4 a1 = make_float4(0.f, 0.f, 0.f, 0.f);
    int e = 0;
    for (; e + 1 < cnt; e += 2) {
        int s0 = s_ent[grp][e], s1 = s_ent[grp][e + 1];
        float4 v0 = *(const float4*)&h[(size_t)s0 * HDIM + j];
        float4 v1 = *(const float4*)&h[(size_t)s1 * HDIM + j];
        a0.x += v0.x; a0.y += v0.y; a0.z += v0.z; a0.w += v0.w;
        a1.x += v1.x; a1.y += v1.y; a1.z += v1.z; a1.w += v1.w;
    }
    if (e < cnt) {
        int s0 = s_ent[grp][e];
        float4 v0 = *(const float4*)&h[(size_t)s0 * HDIM + j];
        a0.x += v0.x; a0.y += v0.y; a0.z += v0.z; a0.w += v0.w;
    }
#pragma unroll
    for (int r = 0; r < 16; r++) {
        int c = s_hist[grp][r];
        if (c) {
            float cf = (float)c;
            float4 rv = *(const float4*)&relv[r * HDIM + j];
            a0.x += cf * rv.x; a0.y += cf * rv.y;
            a0.z += cf * rv.z; a0.w += cf * rv.w;
        }
    }
    float4 acc = make_float4(a0.x + a1.x, a0.y + a1.y, a0.z + a1.z, a0.w + a1.w);

    // emit fp16 hi/lo into pre-tiled A image
    const int mtile = node >> 7, row = node & 127;
    const int kc = t >> 3;
    const uint32_t off = (uint32_t)(row * 64 + (t & 7) * 8);
    uint8_t* cb = g_Aimg + (size_t)(mtile * KCH + kc) * AC;

    __half h0 = __float2half_rn(acc.x), h1 = __float2half_rn(acc.y);
    __half h2 = __float2half_rn(acc.z), h3 = __float2half_rn(acc.w);
    __half l0 = __float2half_rn(acc.x - __half2float(h0));
    __half l1 = __float2half_rn(acc.y - __half2float(h1));
    __half l2 = __float2half_rn(acc.z - __half2float(h2));
    __half l3 = __float2half_rn(acc.w - __half2float(h3));
    *(__half2*)(cb + off)            = __halves2half2(h0, h1);
    *(__half2*)(cb + off + 4)        = __halves2half2(h2, h3);
    *(__half2*)(cb + 8192 + off)     = __halves2half2(l0, l1);
    *(__half2*)(cb + 8192 + off + 4) = __halves2half2(l2, l3);

    float4 hv = *(const float4*)&h[(size_t)node * HDIM + j];
    __half g0 = __float2half_rn(hv.x), g1 = __float2half_rn(hv.y);
    __half g2 = __float2half_rn(hv.z), g3 = __float2half_rn(hv.w);
    __half m0 = __float2half_rn(hv.x - __half2float(g0));
    __half m1 = __float2half_rn(hv.y - __half2float(g1));
    __half m2 = __float2half_rn(hv.z - __half2float(g2));
    __half m3 = __float2half_rn(hv.w - __half2float(g3));
    *(__half2*)(cb + 16384 + off)     = __halves2half2(g0, g1);
    *(__half2*)(cb + 16384 + off + 4) = __halves2half2(g2, g3);
    *(__half2*)(cb + 24576 + off)     = __halves2half2(m0, m1);
    *(__half2*)(cb + 24576 + off + 4) = __halves2half2(m2, m3);
}

// ---------------- kernel 4: weight fp16 B-image emit -------------------------
// B image per (jt,kc): [2 var][96 rows = gate*32+jl][32 fp16]; 0=wih 1=whh.
__global__ void wconv_kernel(const float* __restrict__ w_ih,
                             const float* __restrict__ w_hh) {
    int t = blockIdx.x * blockDim.x + threadIdx.x;
    if (t >= JT * KCH * 2 * 96 * 32) return;
    int kl  = t & 31;
    int r2  = t >> 5;
    int row = r2 % 96;  r2 /= 96;
    int var = r2 & 1;   r2 >>= 1;
    int kc  = r2 & 7;
    int jt  = r2 >> 3;
    int gate = row >> 5, rl = row & 31;

    const float* W = var ? w_hh : w_ih;
    float v = W[(gate * 256 + jt * 32 + rl) * HDIM + kc * 32 + kl];
    *(__half*)(g_Bimg + (size_t)(jt * KCH + kc) * BC +
               var * 6144 + row * 64 + kl * 2) = __float2half_rn(v);
}

// ---------------- chunk loader -----------------------------------------------
__device__ __forceinline__ void load_chunk(uint32_t sb, int stage,
                                           const uint8_t* Ab,
                                           const uint8_t* Bb,
                                           int kc, int tid) {
    const uint8_t* Ag = Ab + (size_t)kc * AC;
#pragma unroll
    for (int i = 0; i < 8; i++) {           // 2048 x 16B
        int idx = tid + i * 256;
        int var = idx >> 9, row = (idx >> 2) & 127, seg = idx & 3;
        cpasync16(sb + stage * A_STG + var * 10240 + row * 80 + seg * 16,
                  Ag + var * 8192 + row * 64 + seg * 16);
    }
    const uint8_t* Bg = Bb + (size_t)kc * BC;
#pragma unroll
    for (int i = 0; i < 3; i++) {           // 768 x 16B
        int idx = tid + i * 256;
        int var = idx / 384, row = (idx >> 2) % 96, seg = idx & 3;
        cpasync16(sb + B_BASE + stage * B_STG + var * 7680 + row * 80 + seg * 16,
                  Bg + var * 6144 + row * 64 + seg * 16);
    }
}

// ---------------- kernel 5: fp16 HMMA dual-GEMM + GRU epilogue ---------------
__global__ __launch_bounds__(256, 1)
void ggnn_mma_kernel(const float* __restrict__ h,
                     const float* __restrict__ b_ih,
                     const float* __restrict__ b_hh,
                     float* __restrict__ out) {
    extern __shared__ __align__(1024) uint8_t sm[];
    const uint32_t sb = smem_u32(sm);
    const int tid   = threadIdx.x;
    const int jtile = blockIdx.x;
    const int mtile = blockIdx.y;
    const int wid   = tid >> 5;
    const int lane  = tid & 31;
    const int lr    = lane >> 2;
    const int lc    = lane & 3;
    const int warp_m = wid & 3;
    const int jhalf  = wid >> 2;

    const uint8_t* Ab = g_Aimg + (size_t)mtile * KCH * AC;
    const uint8_t* Bb = g_Bimg + (size_t)jtile * KCH * BC;

    load_chunk(sb, 0, Ab, Bb, 0, tid); CP_COMMIT();
    load_chunk(sb, 1, Ab, Bb, 1, tid); CP_COMMIT();

    float acc[2][12][4];
#pragma unroll
    for (int a = 0; a < 2; a++)
#pragma unroll
        for (int b = 0; b < 12; b++)
#pragma unroll
            for (int c = 0; c < 4; c++) acc[a][b][c] = 0.0f;

    const int mrow = warp_m * 32;

    for (int c = 0; c < KCH; c++) {
        if (c == KCH - 1) { CP_WAIT0(); } else { CP_WAIT1(); }
        __syncthreads();
        const int s = c & 1;
        const uint32_t* As = (const uint32_t*)(sm + s * A_STG);
        const uint32_t* Bs = (const uint32_t*)(sm + B_BASE + s * B_STG);

#pragma unroll
        for (int kk = 0; kk < 2; kk++) {
            uint32_t afr[4][2][4];   // [var][mt][frag]
#pragma unroll
            for (int var = 0; var < 4; var++)
#pragma unroll
                for (int mt = 0; mt < 2; mt++) {
                    const uint32_t* p = As + var * 2560 +
                                        (mrow + mt * 16 + lr) * 20 + kk * 8 + lc;
                    afr[var][mt][0] = p[0];
                    afr[var][mt][1] = p[160];
                    afr[var][mt][2] = p[4];
                    afr[var][mt][3] = p[164];
                }
#pragma unroll
            for (int g2 = 0; g2 < 2; g2++)
#pragma unroll
                for (int gate = 0; gate < 3; gate++)
#pragma unroll
                    for (int nh = 0; nh < 2; nh++) {
                        const int brow = gate * 32 + jhalf * 16 + nh * 8 + lr;
                        const uint32_t* p = Bs + g2 * 1920 +
                                            brow * 20 + kk * 8 + lc;
                        uint32_t bf[2] = { p[0], p[4] };
                        const int tile = g2 * 6 + gate * 2 + nh;
#pragma unroll
                        for (int mt = 0; mt < 2; mt++) {
                            mma_fp16(acc[mt][tile], afr[2 * g2][mt], bf);
                            mma_fp16(acc[mt][tile], afr[2 * g2 + 1][mt], bf);
                        }
                    }
        }
        __syncthreads();
        if (c + 2 < KCH) { load_chunk(sb, s, Ab, Bb, c + 2, tid); CP_COMMIT(); }
    }

    // ---- GRU epilogue (register-local) ----
    const int jb = jtile * 32 + jhalf * 16;
    float Bsr[2][2], Bsz[2][2], Bin[2][2], Bhn[2][2];
#pragma unroll
    for (int nh = 0; nh < 2; nh++)
#pragma unroll
        for (int cc = 0; cc < 2; cc++) {
            int j = jb + nh * 8 + lc * 2 + cc;
            Bsr[nh][cc] = __ldg(&b_ih[j])       + __ldg(&b_hh[j]);
            Bsz[nh][cc] = __ldg(&b_ih[256 + j]) + __ldg(&b_hh[256 + j]);
            Bin[nh][cc] = __ldg(&b_ih[512 + j]);
            Bhn[nh][cc] = __ldg(&b_hh[512 + j]);
        }

#pragma unroll
    for (int mt = 0; mt < 2; mt++)
#pragma unroll
        for (int rr = 0; rr < 2; rr++) {
            int row = mtile * 128 + mrow + mt * 16 + lr + rr * 8;
            if (row >= N_NODES) continue;
#pragma unroll
            for (int nh = 0; nh < 2; nh++) {
                int j0 = jb + nh * 8 + lc * 2;
                float2 hv = *(const float2*)&h[(size_t)row * HDIM + j0];
                float o[2];
#pragma unroll
                for (int cc = 0; cc < 2; cc++) {
                    int i = rr * 2 + cc;
                    float rg = acc[mt][nh][i]     + acc[mt][6 + nh][i]  + Bsr[nh][cc];
                    float zg = acc[mt][2 + nh][i] + acc[mt][8 + nh][i]  + Bsz[nh][cc];
                    float r  = __fdividef(1.0f, 1.0f + __expf(-rg));
                    float z  = __fdividef(1.0f, 1.0f + __expf(-zg));
                    float ng = acc[mt][4 + nh][i] + Bin[nh][cc] +
                               r * (acc[mt][10 + nh][i] + Bhn[nh][cc]);
                    float ex = __expf(2.0f * ng);
                    float n  = 1.0f - __fdividef(2.0f, ex + 1.0f);
                    float hvv = (cc == 0) ? hv.x : hv.y;
                    o[cc] = (1.0f - z) * n + z * hvv;
                }
                *(float2*)&out[(size_t)row * HDIM + j0] = make_float2(o[0], o[1]);
            }
        }
}

// ---------------- launch ------------------------------------------------------
extern "C" void kernel_launch(void* const* d_in, const int* in_sizes, int n_in,
                              void* d_out, int out_size) {
    const float* h    = (const float*)d_in[0];
    const float* relv = (const float*)d_in[1];
    const float* w_ih = (const float*)d_in[2];
    const float* w_hh = (const float*)d_in[3];
    const float* b_ih = (const float*)d_in[4];
    const float* b_hh = (const float*)d_in[5];
    const int*   esrc = (const int*)d_in[6];
    const int*   edst = (const int*)d_in[7];
    const int*   erel = (const int*)d_in[8];
    float*       out  = (float*)d_out;

    cudaFuncSetAttribute(ggnn_mma_kernel,
                         cudaFuncAttributeMaxDynamicSharedMemorySize, SMEM_TOTAL);

    zero_cnt_kernel<<<(N_NODES + 255) / 256, 256>>>();
    build_buckets_kernel<<<(N_EDGES + 255) / 256, 256>>>(esrc, edst, erel);
    wconv_kernel<<<(JT * KCH * 2 * 96 * 32 + 255) / 256, 256>>>(w_ih, w_hh);
    reduce_convert_kernel<<<N_NODES / 4, 256>>>(h, relv);

    dim3 grid(JT, MT);
    ggnn_mma_kernel<<<grid, 256, SMEM_TOTAL>>>(h, b_ih, b_hh, out);
}

// round 5
// speedup vs baseline: 3.4438x; 1.3307x over previous
#include <cuda_runtime.h>
#include <cuda_fp16.h>
#include <math.h>
#include <stdint.h>

#define N_NODES 50000
#define N_EDGES 800000
#define HDIM    256
#define CAP     64

#define MT 391          // m-tiles of 128 rows
#define JT 8            // j-tiles of 32 output dims
#define KCH 8           // k-chunks of 32
#define AC 16384        // A chunk: 2 var (red, h) x 128 rows x 64B
#define BC 12288        // B chunk: 2 var (wih, whh) x 96 rows x 64B

// smem: A stages then B stages; row stride 80B -> conflict-free LDS.
#define A_STG  20480    // 2 var x 128 x 80
#define B_STG  15360    // 2 var x 96 x 80
#define B_BASE 40960
#define SMEM_TOTAL 71680

// ---------------- device scratch (static; no allocation) --------------------
__device__ int g_cnt[N_NODES];
__device__ int g_bucket[N_NODES * CAP];
__device__ __align__(16) uint8_t g_Aimg[(size_t)MT * KCH * AC]; // ~51 MB
__device__ __align__(16) uint8_t g_Bimg[(size_t)JT * KCH * BC]; // ~0.8 MB

// ---------------- PTX helpers (sm_80-level only) -----------------------------
__device__ __forceinline__ uint32_t smem_u32(const void* p) {
    uint32_t a;
    asm("{ .reg .u64 t; cvta.to.shared.u64 t, %1; cvt.u32.u64 %0, t; }"
        : "=r"(a) : "l"(p));
    return a;
}
__device__ __forceinline__ void cpasync16(uint32_t dst, const void* src) {
    asm volatile("cp.async.cg.shared.global [%0], [%1], 16;"
                 :: "r"(dst), "l"(src) : "memory");
}
#define CP_COMMIT() asm volatile("cp.async.commit_group;" ::: "memory")
#define CP_WAIT1()  asm volatile("cp.async.wait_group 1;" ::: "memory")
#define CP_WAIT0()  asm volatile("cp.async.wait_group 0;" ::: "memory")

__device__ __forceinline__ void mma_fp16(float* d, const uint32_t* a,
                                         const uint32_t* b) {
    asm volatile(
        "mma.sync.aligned.m16n8k16.row.col.f32.f16.f16.f32 "
        "{%0,%1,%2,%3}, {%4,%5,%6,%7}, {%8,%9}, {%0,%1,%2,%3};"
        : "+f"(d[0]), "+f"(d[1]), "+f"(d[2]), "+f"(d[3])
        : "r"(a[0]), "r"(a[1]), "r"(a[2]), "r"(a[3]), "r"(b[0]), "r"(b[1]));
}

// ---------------- kernel 1: zero counters ------------------------------------
__global__ void zero_cnt_kernel() {
    int i = blockIdx.x * blockDim.x + threadIdx.x;
    if (i < N_NODES) g_cnt[i] = 0;
}

// ---------------- kernel 2: bucket edges by destination ----------------------
__global__ void build_buckets_kernel(const int* __restrict__ esrc,
                                     const int* __restrict__ edst,
                                     const int* __restrict__ erel) {
    int i = blockIdx.x * blockDim.x + threadIdx.x;
    if (i >= N_EDGES) return;
    int d   = edst[i];
    int pos = atomicAdd(&g_cnt[d], 1);
    if (pos < CAP) g_bucket[d * CAP + pos] = esrc[i] | (erel[i] << 20);
}

// ---------------- kernel 3: segment reduce + fp16 A-image emit ---------------
// 4 nodes per block; 64 threads per node; thread owns 4 contiguous dims.
// relvector adds collapsed into a 16-bin histogram; 4 gather streams in flight.
__global__ __launch_bounds__(256)
void reduce_convert_kernel(const float* __restrict__ h,
                           const float* __restrict__ relv) {
    const int grp  = threadIdx.x >> 6;
    const int t    = threadIdx.x & 63;
    const int node = blockIdx.x * 4 + grp;
    const int j    = t * 4;

    __shared__ int s_ent[4][CAP];
    __shared__ int s_hist[4][16];
    __shared__ int s_cnt[4];

    if (t == 0) {
        int c = g_cnt[node];
        s_cnt[grp] = c < CAP ? c : CAP;
    }
    if (t < 16) s_hist[grp][t] = 0;
    __syncthreads();

    const int cnt = s_cnt[grp];
    for (int e = t; e < cnt; e += 64) {
        int en = g_bucket[node * CAP + e];
        s_ent[grp][e] = en & 0xFFFFF;
        atomicAdd(&s_hist[grp][en >> 20], 1);
    }
    __syncthreads();

    float4 a0 = make_float4(0.f, 0.f, 0.f, 0.f);
    float4 a1 = make_float4(0.f, 0.f, 0.f, 0.f);
    float4 a2 = make_float4(0.f, 0.f, 0.f, 0.f);
    float4 a3 = make_float4(0.f, 0.f, 0.f, 0.f);
    int e = 0;
    for (; e + 3 < cnt; e += 4) {
        int s0 = s_ent[grp][e],     s1 = s_ent[grp][e + 1];
        int s2 = s_ent[grp][e + 2], s3 = s_ent[grp][e + 3];
        float4 v0 = *(const float4*)&h[(size_t)s0 * HDIM + j];
        float4 v1 = *(const float4*)&h[(size_t)s1 * HDIM + j];
        float4 v2 = *(const float4*)&h[(size_t)s2 * HDIM + j];
        float4 v3 = *(const float4*)&h[(size_t)s3 * HDIM + j];
        a0.x += v0.x; a0.y += v0.y; a0.z += v0.z; a0.w += v0.w;
        a1.x += v1.x; a1.y += v1.y; a1.z += v1.z; a1.w += v1.w;
        a2.x += v2.x; a2.y += v2.y; a2.z += v2.z; a2.w += v2.w;
        a3.x += v3.x; a3.y += v3.y; a3.z += v3.z; a3.w += v3.w;
    }
    for (; e < cnt; e++) {
        int s0 = s_ent[grp][e];
        float4 v0 = *(const float4*)&h[(size_t)s0 * HDIM + j];
        a0.x += v0.x; a0.y += v0.y; a0.z += v0.z; a0.w += v0.w;
    }
#pragma unroll
    for (int r = 0; r < 16; r++) {
        int c = s_hist[grp][r];
        if (c) {
            float cf = (float)c;
            float4 rv = *(const float4*)&relv[r * HDIM + j];
            a1.x += cf * rv.x; a1.y += cf * rv.y;
            a1.z += cf * rv.z; a1.w += cf * rv.w;
        }
    }
    float4 acc = make_float4(a0.x + a1.x + a2.x + a3.x,
                             a0.y + a1.y + a2.y + a3.y,
                             a0.z + a1.z + a2.z + a3.z,
                             a0.w + a1.w + a2.w + a3.w);

    // emit fp16 into pre-tiled A image (var0 = red, var1 = h)
    const int mtile = node >> 7, row = node & 127;
    const int kc = t >> 3;
    const uint32_t off = (uint32_t)(row * 64 + (t & 7) * 8);
    uint8_t* cb = g_Aimg + (size_t)(mtile * KCH + kc) * AC;

    *(__half2*)(cb + off)     = __halves2half2(__float2half_rn(acc.x),
                                               __float2half_rn(acc.y));
    *(__half2*)(cb + off + 4) = __halves2half2(__float2half_rn(acc.z),
                                               __float2half_rn(acc.w));

    float4 hv = *(const float4*)&h[(size_t)node * HDIM + j];
    *(__half2*)(cb + 8192 + off)     = __halves2half2(__float2half_rn(hv.x),
                                                      __float2half_rn(hv.y));
    *(__half2*)(cb + 8192 + off + 4) = __halves2half2(__float2half_rn(hv.z),
                                                      __float2half_rn(hv.w));
}

// ---------------- kernel 4: weight fp16 B-image emit -------------------------
__global__ void wconv_kernel(const float* __restrict__ w_ih,
                             const float* __restrict__ w_hh) {
    int t = blockIdx.x * blockDim.x + threadIdx.x;
    if (t >= JT * KCH * 2 * 96 * 32) return;
    int kl  = t & 31;
    int r2  = t >> 5;
    int row = r2 % 96;  r2 /= 96;
    int var = r2 & 1;   r2 >>= 1;
    int kc  = r2 & 7;
    int jt  = r2 >> 3;
    int gate = row >> 5, rl = row & 31;

    const float* W = var ? w_hh : w_ih;
    float v = W[(gate * 256 + jt * 32 + rl) * HDIM + kc * 32 + kl];
    *(__half*)(g_Bimg + (size_t)(jt * KCH + kc) * BC +
               var * 6144 + row * 64 + kl * 2) = __float2half_rn(v);
}

// ---------------- chunk loader -----------------------------------------------
__device__ __forceinline__ void load_chunk(uint32_t sb, int stage,
                                           const uint8_t* Ab,
                                           const uint8_t* Bb,
                                           int kc, int tid) {
    const uint8_t* Ag = Ab + (size_t)kc * AC;
#pragma unroll
    for (int i = 0; i < 4; i++) {           // 1024 x 16B
        int idx = tid + i * 256;
        int var = idx >> 9, row = (idx >> 2) & 127, seg = idx & 3;
        cpasync16(sb + stage * A_STG + var * 10240 + row * 80 + seg * 16,
                  Ag + var * 8192 + row * 64 + seg * 16);
    }
    const uint8_t* Bg = Bb + (size_t)kc * BC;
#pragma unroll
    for (int i = 0; i < 3; i++) {           // 768 x 16B
        int idx = tid + i * 256;
        int var = idx / 384, row = (idx >> 2) % 96, seg = idx & 3;
        cpasync16(sb + B_BASE + stage * B_STG + var * 7680 + row * 80 + seg * 16,
                  Bg + var * 6144 + row * 64 + seg * 16);
    }
}

// ---------------- kernel 5: fp16 HMMA dual-GEMM + GRU epilogue ---------------
__global__ __launch_bounds__(256, 1)
void ggnn_mma_kernel(const float* __restrict__ h,
                     const float* __restrict__ b_ih,
                     const float* __restrict__ b_hh,
                     float* __restrict__ out) {
    extern __shared__ __align__(1024) uint8_t sm[];
    const uint32_t sb = smem_u32(sm);
    const int tid   = threadIdx.x;
    const int jtile = blockIdx.x;
    const int mtile = blockIdx.y;
    const int wid   = tid >> 5;
    const int lane  = tid & 31;
    const int lr    = lane >> 2;
    const int lc    = lane & 3;
    const int warp_m = wid & 3;
    const int jhalf  = wid >> 2;

    const uint8_t* Ab = g_Aimg + (size_t)mtile * KCH * AC;
    const uint8_t* Bb = g_Bimg + (size_t)jtile * KCH * BC;

    load_chunk(sb, 0, Ab, Bb, 0, tid); CP_COMMIT();
    load_chunk(sb, 1, Ab, Bb, 1, tid); CP_COMMIT();

    float acc[2][12][4];
#pragma unroll
    for (int a = 0; a < 2; a++)
#pragma unroll
        for (int b = 0; b < 12; b++)
#pragma unroll
            for (int c = 0; c < 4; c++) acc[a][b][c] = 0.0f;

    const int mrow = warp_m * 32;

    for (int c = 0; c < KCH; c++) {
        if (c == KCH - 1) { CP_WAIT0(); } else { CP_WAIT1(); }
        __syncthreads();
        const int s = c & 1;
        const uint32_t* As = (const uint32_t*)(sm + s * A_STG);
        const uint32_t* Bs = (const uint32_t*)(sm + B_BASE + s * B_STG);

#pragma unroll
        for (int kk = 0; kk < 2; kk++) {
            uint32_t afr[2][2][4];   // [var: 0=red 1=h][mt][frag]
#pragma unroll
            for (int var = 0; var < 2; var++)
#pragma unroll
                for (int mt = 0; mt < 2; mt++) {
                    const uint32_t* p = As + var * 2560 +
                                        (mrow + mt * 16 + lr) * 20 + kk * 8 + lc;
                    afr[var][mt][0] = p[0];
                    afr[var][mt][1] = p[160];
                    afr[var][mt][2] = p[4];
                    afr[var][mt][3] = p[164];
                }
#pragma unroll
            for (int g2 = 0; g2 < 2; g2++)
#pragma unroll
                for (int gate = 0; gate < 3; gate++)
#pragma unroll
                    for (int nh = 0; nh < 2; nh++) {
                        const int brow = gate * 32 + jhalf * 16 + nh * 8 + lr;
                        const uint32_t* p = Bs + g2 * 1920 +
                                            brow * 20 + kk * 8 + lc;
                        uint32_t bf[2] = { p[0], p[4] };
                        const int tile = g2 * 6 + gate * 2 + nh;
#pragma unroll
                        for (int mt = 0; mt < 2; mt++)
                            mma_fp16(acc[mt][tile], afr[g2][mt], bf);
                    }
        }
        __syncthreads();
        if (c + 2 < KCH) { load_chunk(sb, s, Ab, Bb, c + 2, tid); CP_COMMIT(); }
    }

    // ---- GRU epilogue (register-local) ----
    const int jb = jtile * 32 + jhalf * 16;
    float Bsr[2][2], Bsz[2][2], Bin[2][2], Bhn[2][2];
#pragma unroll
    for (int nh = 0; nh < 2; nh++)
#pragma unroll
        for (int cc = 0; cc < 2; cc++) {
            int j = jb + nh * 8 + lc * 2 + cc;
            Bsr[nh][cc] = __ldg(&b_ih[j])       + __ldg(&b_hh[j]);
            Bsz[nh][cc] = __ldg(&b_ih[256 + j]) + __ldg(&b_hh[256 + j]);
            Bin[nh][cc] = __ldg(&b_ih[512 + j]);
            Bhn[nh][cc] = __ldg(&b_hh[512 + j]);
        }

#pragma unroll
    for (int mt = 0; mt < 2; mt++)
#pragma unroll
        for (int rr = 0; rr < 2; rr++) {
            int row = mtile * 128 + mrow + mt * 16 + lr + rr * 8;
            if (row >= N_NODES) continue;
#pragma unroll
            for (int nh = 0; nh < 2; nh++) {
                int j0 = jb + nh * 8 + lc * 2;
                float2 hv = *(const float2*)&h[(size_t)row * HDIM + j0];
                float o[2];
#pragma unroll
                for (int cc = 0; cc < 2; cc++) {
                    int i = rr * 2 + cc;
                    float rg = acc[mt][nh][i]     + acc[mt][6 + nh][i]  + Bsr[nh][cc];
                    float zg = acc[mt][2 + nh][i] + acc[mt][8 + nh][i]  + Bsz[nh][cc];
                    float r  = __fdividef(1.0f, 1.0f + __expf(-rg));
                    float z  = __fdividef(1.0f, 1.0f + __expf(-zg));
                    float ng = acc[mt][4 + nh][i] + Bin[nh][cc] +
                               r * (acc[mt][10 + nh][i] + Bhn[nh][cc]);
                    float ex = __expf(2.0f * ng);
                    float n  = 1.0f - __fdividef(2.0f, ex + 1.0f);
                    float hvv = (cc == 0) ? hv.x : hv.y;
                    o[cc] = (1.0f - z) * n + z * hvv;
                }
                *(float2*)&out[(size_t)row * HDIM + j0] = make_float2(o[0], o[1]);
            }
        }
}

// ---------------- launch ------------------------------------------------------
extern "C" void kernel_launch(void* const* d_in, const int* in_sizes, int n_in,
                              void* d_out, int out_size) {
    const float* h    = (const float*)d_in[0];
    const float* relv = (const float*)d_in[1];
    const float* w_ih = (const float*)d_in[2];
    const float* w_hh = (const float*)d_in[3];
    const float* b_ih = (const float*)d_in[4];
    const float* b_hh = (const float*)d_in[5];
    const int*   esrc = (const int*)d_in[6];
    const int*   edst = (const int*)d_in[7];
    const int*   erel = (const int*)d_in[8];
    float*       out  = (float*)d_out;

    cudaFuncSetAttribute(ggnn_mma_kernel,
                         cudaFuncAttributeMaxDynamicSharedMemorySize, SMEM_TOTAL);

    zero_cnt_kernel<<<(N_NODES + 255) / 256, 256>>>();
    build_buckets_kernel<<<(N_EDGES + 255) / 256, 256>>>(esrc, edst, erel);
    wconv_kernel<<<(JT * KCH * 2 * 96 * 32 + 255) / 256, 256>>>(w_ih, w_hh);
    reduce_convert_kernel<<<N_NODES / 4, 256>>>(h, relv);

    dim3 grid(JT, MT);
    ggnn_mma_kernel<<<grid, 256, SMEM_TOTAL>>>(h, b_ih, b_hh, out);
}

// round 6
// speedup vs baseline: 4.0235x; 1.1683x over previous
#include <cuda_runtime.h>
#include <cuda_fp16.h>
#include <math.h>
#include <stdint.h>

#define N_NODES 50000
#define N_EDGES 800000
#define HDIM    256
#define CAP     64

#define MT 391          // m-tiles of 128 rows
#define JT 16           // j-tiles of 16 output dims
#define KCH 8           // k-chunks of 32
#define BC  6144        // B chunk: 2 var x 48 rows x 64B

// smem: A stages (2 var x 128 rows x 80B) then B stages (2 var x 48 x 80B)
#define A_STG  20480
#define B_STG  7680
#define B_BASE 40960
#define SMEM_TOTAL 56320

// ---------------- device scratch (static; no allocation) --------------------
__device__ int g_cnt[N_NODES];
__device__ int g_bucket[N_NODES * CAP];
__device__ __align__(16) uint8_t g_h16[(size_t)50048 * 512];    // h in fp16 rows
__device__ __align__(16) uint8_t g_red16[(size_t)50048 * 512];  // red in fp16 rows
__device__ __align__(16) uint8_t g_Bimg[(size_t)JT * KCH * BC]; // weights fp16

// ---------------- PTX helpers (sm_80-level only) -----------------------------
__device__ __forceinline__ uint32_t smem_u32(const void* p) {
    uint32_t a;
    asm("{ .reg .u64 t; cvta.to.shared.u64 t, %1; cvt.u32.u64 %0, t; }"
        : "=r"(a) : "l"(p));
    return a;
}
__device__ __forceinline__ void cpasync16(uint32_t dst, const void* src) {
    asm volatile("cp.async.cg.shared.global [%0], [%1], 16;"
                 :: "r"(dst), "l"(src) : "memory");
}
#define CP_COMMIT() asm volatile("cp.async.commit_group;" ::: "memory")
#define CP_WAIT1()  asm volatile("cp.async.wait_group 1;" ::: "memory")
#define CP_WAIT0()  asm volatile("cp.async.wait_group 0;" ::: "memory")

__device__ __forceinline__ void ldmx4(uint32_t* r, uint32_t addr) {
    asm volatile("ldmatrix.sync.aligned.m8n8.x4.shared.b16 {%0,%1,%2,%3}, [%4];"
                 : "=r"(r[0]), "=r"(r[1]), "=r"(r[2]), "=r"(r[3]) : "r"(addr));
}
__device__ __forceinline__ void ldmx2(uint32_t* r, uint32_t addr) {
    asm volatile("ldmatrix.sync.aligned.m8n8.x2.shared.b16 {%0,%1}, [%2];"
                 : "=r"(r[0]), "=r"(r[1]) : "r"(addr));
}
__device__ __forceinline__ void mma_fp16(float* d, const uint32_t* a,
                                         const uint32_t* b) {
    asm volatile(
        "mma.sync.aligned.m16n8k16.row.col.f32.f16.f16.f32 "
        "{%0,%1,%2,%3}, {%4,%5,%6,%7}, {%8,%9}, {%0,%1,%2,%3};"
        : "+f"(d[0]), "+f"(d[1]), "+f"(d[2]), "+f"(d[3])
        : "r"(a[0]), "r"(a[1]), "r"(a[2]), "r"(a[3]), "r"(b[0]), "r"(b[1]));
}

// ---------------- kernel 1: zero counters ------------------------------------
__global__ void zero_cnt_kernel() {
    int i = blockIdx.x * blockDim.x + threadIdx.x;
    if (i < N_NODES) g_cnt[i] = 0;
}

// ---------------- kernel 2: bucket edges by destination ----------------------
__global__ void build_buckets_kernel(const int* __restrict__ esrc,
                                     const int* __restrict__ edst,
                                     const int* __restrict__ erel) {
    int i = blockIdx.x * blockDim.x + threadIdx.x;
    if (i >= N_EDGES) return;
    int d   = edst[i];
    int pos = atomicAdd(&g_cnt[d], 1);
    if (pos < CAP) g_bucket[d * CAP + pos] = esrc[i] | (erel[i] << 20);
}

// ---------------- kernel 3: h -> fp16 row image -------------------------------
__global__ void h16conv_kernel(const float* __restrict__ h) {
    int i = blockIdx.x * blockDim.x + threadIdx.x;   // one group of 8 floats
    if (i >= N_NODES * HDIM / 8) return;
    const float4* p = (const float4*)(h + (size_t)i * 8);
    float4 v0 = p[0], v1 = p[1];
    __half2 h0 = __float22half2_rn(make_float2(v0.x, v0.y));
    __half2 h1 = __float22half2_rn(make_float2(v0.z, v0.w));
    __half2 h2 = __float22half2_rn(make_float2(v1.x, v1.y));
    __half2 h3 = __float22half2_rn(make_float2(v1.z, v1.w));
    uint4 o;
    o.x = *(uint32_t*)&h0; o.y = *(uint32_t*)&h1;
    o.z = *(uint32_t*)&h2; o.w = *(uint32_t*)&h3;
    *(uint4*)(g_h16 + (size_t)i * 16) = o;
}

// ---------------- kernel 4: segment reduce (fp16 gather) ----------------------
// One warp per node; lane owns 8 dims (16B). relvectors via 16-bin histogram.
__global__ __launch_bounds__(256)
void reduce_convert_kernel(const float* __restrict__ relv) {
    const int wid  = threadIdx.x >> 5;
    const int lane = threadIdx.x & 31;
    const int node = blockIdx.x * 8 + wid;

    __shared__ int s_ent[8][CAP];
    __shared__ int s_hist[8][16];

    if (lane < 16) s_hist[wid][lane] = 0;
    int cnt = g_cnt[node];
    cnt = cnt < CAP ? cnt : CAP;
    __syncwarp();
    if (lane < cnt) {
        int en = g_bucket[node * CAP + lane];
        s_ent[wid][lane] = en & 0xFFFFF;
        atomicAdd(&s_hist[wid][en >> 20], 1);
    }
    if (lane + 32 < cnt) {
        int en = g_bucket[node * CAP + lane + 32];
        s_ent[wid][lane + 32] = en & 0xFFFFF;
        atomicAdd(&s_hist[wid][en >> 20], 1);
    }
    __syncwarp();

    float a0[8], a1[8];
#pragma unroll
    for (int q = 0; q < 8; q++) { a0[q] = 0.f; a1[q] = 0.f; }

    int e = 0;
    for (; e + 1 < cnt; e += 2) {
        uint4 v0 = *(const uint4*)(g_h16 + (size_t)s_ent[wid][e]     * 512 + lane * 16);
        uint4 v1 = *(const uint4*)(g_h16 + (size_t)s_ent[wid][e + 1] * 512 + lane * 16);
        const __half2* p0 = (const __half2*)&v0;
        const __half2* p1 = (const __half2*)&v1;
#pragma unroll
        for (int q = 0; q < 4; q++) {
            float2 f0 = __half22float2(p0[q]);
            float2 f1 = __half22float2(p1[q]);
            a0[2 * q] += f0.x; a0[2 * q + 1] += f0.y;
            a1[2 * q] += f1.x; a1[2 * q + 1] += f1.y;
        }
    }
    if (e < cnt) {
        uint4 v0 = *(const uint4*)(g_h16 + (size_t)s_ent[wid][e] * 512 + lane * 16);
        const __half2* p0 = (const __half2*)&v0;
#pragma unroll
        for (int q = 0; q < 4; q++) {
            float2 f0 = __half22float2(p0[q]);
            a0[2 * q] += f0.x; a0[2 * q + 1] += f0.y;
        }
    }
    const int j = lane * 8;
#pragma unroll
    for (int r = 0; r < 16; r++) {
        int c = s_hist[wid][r];
        if (c) {
            float cf = (float)c;
            float4 r0 = *(const float4*)&relv[r * HDIM + j];
            float4 r1 = *(const float4*)&relv[r * HDIM + j + 4];
            a1[0] += cf * r0.x; a1[1] += cf * r0.y;
            a1[2] += cf * r0.z; a1[3] += cf * r0.w;
            a1[4] += cf * r1.x; a1[5] += cf * r1.y;
            a1[6] += cf * r1.z; a1[7] += cf * r1.w;
        }
    }
    __half2 o0 = __float22half2_rn(make_float2(a0[0] + a1[0], a0[1] + a1[1]));
    __half2 o1 = __float22half2_rn(make_float2(a0[2] + a1[2], a0[3] + a1[3]));
    __half2 o2 = __float22half2_rn(make_float2(a0[4] + a1[4], a0[5] + a1[5]));
    __half2 o3 = __float22half2_rn(make_float2(a0[6] + a1[6], a0[7] + a1[7]));
    uint4 o;
    o.x = *(uint32_t*)&o0; o.y = *(uint32_t*)&o1;
    o.z = *(uint32_t*)&o2; o.w = *(uint32_t*)&o3;
    *(uint4*)(g_red16 + (size_t)node * 512 + lane * 16) = o;
}

// ---------------- kernel 5: weight fp16 B-image emit --------------------------
// B image per (jt,kc): [2 var][48 rows = gate*16 + jl][32 fp16].
__global__ void wconv_kernel(const float* __restrict__ w_ih,
                             const float* __restrict__ w_hh) {
    int t = blockIdx.x * blockDim.x + threadIdx.x;
    if (t >= JT * KCH * 2 * 48 * 32) return;
    int kl  = t & 31;
    int r2  = t >> 5;
    int row = r2 % 48;  r2 /= 48;
    int var = r2 & 1;   r2 >>= 1;
    int kc  = r2 & 7;
    int jt  = r2 >> 3;
    int gate = row / 16, rl = row % 16;

    const float* W = var ? w_hh : w_ih;
    float v = W[(gate * 256 + jt * 16 + rl) * HDIM + kc * 32 + kl];
    *(__half*)(g_Bimg + (size_t)(jt * KCH + kc) * BC +
               var * 3072 + row * 64 + kl * 2) = __float2half_rn(v);
}

// ---------------- chunk loader ------------------------------------------------
__device__ __forceinline__ void load_chunk(uint32_t sb, int stage,
                                           const uint8_t* redp,
                                           const uint8_t* hp,
                                           const uint8_t* Bb,
                                           int kc, int tid) {
#pragma unroll
    for (int i = 0; i < 4; i++) {           // A: 1024 x 16B
        int idx = tid + i * 256;
        int var = idx >> 9, row = (idx >> 2) & 127, seg = idx & 3;
        const uint8_t* src = (var ? hp : redp) +
                             (size_t)row * 512 + kc * 64 + seg * 16;
        cpasync16(sb + stage * A_STG + var * 10240 + row * 80 + seg * 16, src);
    }
    const uint8_t* Bg = Bb + (size_t)kc * BC;
#pragma unroll
    for (int i = 0; i < 2; i++) {           // B: 384 x 16B
        int idx = tid + i * 256;
        if (idx < 384) {
            int var = idx / 192, rem = idx % 192;
            int row = rem >> 2, seg = rem & 3;
            cpasync16(sb + B_BASE + stage * B_STG + var * 3840 + row * 80 + seg * 16,
                      Bg + var * 3072 + row * 64 + seg * 16);
        }
    }
}

// ---------------- kernel 6: fp16 HMMA dual-GEMM + GRU epilogue ----------------
__global__ __launch_bounds__(256, 3)
void ggnn_mma_kernel(const float* __restrict__ h,
                     const float* __restrict__ b_ih,
                     const float* __restrict__ b_hh,
                     float* __restrict__ out) {
    extern __shared__ __align__(1024) uint8_t sm[];
    const uint32_t sb = smem_u32(sm);
    const int tid   = threadIdx.x;
    const int jtile = blockIdx.x;
    const int mtile = blockIdx.y;
    const int wid   = tid >> 5;
    const int lane  = tid & 31;
    const int lr    = lane >> 2;
    const int lc    = lane & 3;
    const int warp_m = wid & 3;     // 32-row slice
    const int jhalf  = wid >> 2;    // 8-col half of the 16-col j-tile

    const uint8_t* redp = g_red16 + (size_t)mtile * 128 * 512;
    const uint8_t* hp   = g_h16   + (size_t)mtile * 128 * 512;
    const uint8_t* Bb   = g_Bimg  + (size_t)jtile * KCH * BC;

    load_chunk(sb, 0, redp, hp, Bb, 0, tid); CP_COMMIT();
    load_chunk(sb, 1, redp, hp, Bb, 1, tid); CP_COMMIT();

    float acc[2][6][4];   // [mt][g2*3+gate][frag]
#pragma unroll
    for (int a = 0; a < 2; a++)
#pragma unroll
        for (int b = 0; b < 6; b++)
#pragma unroll
            for (int c = 0; c < 4; c++) acc[a][b][c] = 0.0f;

    const int mrow = warp_m * 32;

    for (int c = 0; c < KCH; c++) {
        if (c == KCH - 1) { CP_WAIT0(); } else { CP_WAIT1(); }
        __syncthreads();
        const int s = c & 1;
        const uint32_t abase = sb + s * A_STG +
                               (mrow + (lane & 15)) * 80 + (lane >> 4) * 16;
        const uint32_t bbase = sb + B_BASE + s * B_STG +
                               (jhalf * 8 + (lane & 7)) * 80 + ((lane >> 3) & 1) * 16;

#pragma unroll
        for (int kk = 0; kk < 2; kk++) {
            uint32_t afr[2][2][4];   // [var: 0=red 1=h][mt][frag]
#pragma unroll
            for (int var = 0; var < 2; var++)
#pragma unroll
                for (int mt = 0; mt < 2; mt++)
                    ldmx4(afr[var][mt],
                          abase + var * 10240 + mt * 16 * 80 + kk * 32);
#pragma unroll
            for (int g2 = 0; g2 < 2; g2++)
#pragma unroll
                for (int gate = 0; gate < 3; gate++) {
                    uint32_t bf[2];
                    ldmx2(bf, bbase + g2 * 3840 + gate * 16 * 80 + kk * 32);
                    const int tile = g2 * 3 + gate;
#pragma unroll
                    for (int mt = 0; mt < 2; mt++)
                        mma_fp16(acc[mt][tile], afr[g2][mt], bf);
                }
        }
        __syncthreads();
        if (c + 2 < KCH) {
            load_chunk(sb, s, redp, hp, Bb, c + 2, tid);
            CP_COMMIT();
        }
    }

    // ---- GRU epilogue (register-local) ----
    const int jb = jtile * 16 + jhalf * 8;
    float Bsr[2], Bsz[2], Bin[2], Bhn[2];
#pragma unroll
    for (int cc = 0; cc < 2; cc++) {
        int j = jb + lc * 2 + cc;
        Bsr[cc] = __ldg(&b_ih[j])       + __ldg(&b_hh[j]);
        Bsz[cc] = __ldg(&b_ih[256 + j]) + __ldg(&b_hh[256 + j]);
        Bin[cc] = __ldg(&b_ih[512 + j]);
        Bhn[cc] = __ldg(&b_hh[512 + j]);
    }

#pragma unroll
    for (int mt = 0; mt < 2; mt++)
#pragma unroll
        for (int rr = 0; rr < 2; rr++) {
            int row = mtile * 128 + mrow + mt * 16 + lr + rr * 8;
            if (row >= N_NODES) continue;
            int j0 = jb + lc * 2;
            float2 hv = *(const float2*)&h[(size_t)row * HDIM + j0];
            float o[2];
#pragma unroll
            for (int cc = 0; cc < 2; cc++) {
                int i = rr * 2 + cc;
                float rg = acc[mt][0][i] + acc[mt][3][i] + Bsr[cc];
                float zg = acc[mt][1][i] + acc[mt][4][i] + Bsz[cc];
                float r  = __fdividef(1.0f, 1.0f + __expf(-rg));
                float z  = __fdividef(1.0f, 1.0f + __expf(-zg));
                float ng = acc[mt][2][i] + Bin[cc] +
                           r * (acc[mt][5][i] + Bhn[cc]);
                float ex = __expf(2.0f * ng);
                float n  = 1.0f - __fdividef(2.0f, ex + 1.0f);
                float hvv = (cc == 0) ? hv.x : hv.y;
                o[cc] = (1.0f - z) * n + z * hvv;
            }
            *(float2*)&out[(size_t)row * HDIM + j0] = make_float2(o[0], o[1]);
        }
}

// ---------------- launch --------------------------------------------------------
extern "C" void kernel_launch(void* const* d_in, const int* in_sizes, int n_in,
                              void* d_out, int out_size) {
    const float* h    = (const float*)d_in[0];
    const float* relv = (const float*)d_in[1];
    const float* w_ih = (const float*)d_in[2];
    const float* w_hh = (const float*)d_in[3];
    const float* b_ih = (const float*)d_in[4];
    const float* b_hh = (const float*)d_in[5];
    const int*   esrc = (const int*)d_in[6];
    const int*   edst = (const int*)d_in[7];
    const int*   erel = (const int*)d_in[8];
    float*       out  = (float*)d_out;

    cudaFuncSetAttribute(ggnn_mma_kernel,
                         cudaFuncAttributeMaxDynamicSharedMemorySize, SMEM_TOTAL);

    zero_cnt_kernel<<<(N_NODES + 255) / 256, 256>>>();
    build_buckets_kernel<<<(N_EDGES + 255) / 256, 256>>>(esrc, edst, erel);
    h16conv_kernel<<<(N_NODES * HDIM / 8 + 255) / 256, 256>>>(h);
    wconv_kernel<<<(JT * KCH * 2 * 48 * 32 + 255) / 256, 256>>>(w_ih, w_hh);
    reduce_convert_kernel<<<N_NODES / 8, 256>>>(relv);

    dim3 grid(JT, MT);
    ggnn_mma_kernel<<<grid, 256, SMEM_TOTAL>>>(h, b_ih, b_hh, out);
}

// round 7
// speedup vs baseline: 4.0456x; 1.0055x over previous
#include <cuda_runtime.h>
#include <cuda_fp16.h>
#include <math.h>
#include <stdint.h>

#define N_NODES 50000
#define N_EDGES 800000
#define HDIM    256
#define CAP     64

#define MT 391          // m-tiles of 128 rows
#define JT 16           // j-tiles of 16 output dims
#define KCH 8           // k-chunks of 32
#define BC  6144        // B chunk: 2 var x 48 rows x 64B

// smem: A stages (2 var x 128 rows x 80B) then B stages (2 var x 48 x 80B)
#define A_STG  20480
#define B_STG  7680
#define B_BASE 40960
#define SMEM_TOTAL 56320

// ---------------- device scratch (static; no allocation) --------------------
__device__ int g_cnt[N_NODES];
__device__ int g_bucket[N_NODES * CAP];
__device__ __align__(16) uint8_t g_h16[(size_t)50048 * 512];    // h in fp16 rows
__device__ __align__(16) uint8_t g_red16[(size_t)50048 * 512];  // red in fp16 rows
__device__ __align__(16) uint8_t g_Bimg[(size_t)JT * KCH * BC]; // weights fp16

// ---------------- PTX helpers (sm_80-level only) -----------------------------
__device__ __forceinline__ uint32_t smem_u32(const void* p) {
    uint32_t a;
    asm("{ .reg .u64 t; cvta.to.shared.u64 t, %1; cvt.u32.u64 %0, t; }"
        : "=r"(a) : "l"(p));
    return a;
}
__device__ __forceinline__ void cpasync16(uint32_t dst, const void* src) {
    asm volatile("cp.async.cg.shared.global [%0], [%1], 16;"
                 :: "r"(dst), "l"(src) : "memory");
}
#define CP_COMMIT() asm volatile("cp.async.commit_group;" ::: "memory")
#define CP_WAIT1()  asm volatile("cp.async.wait_group 1;" ::: "memory")
#define CP_WAIT0()  asm volatile("cp.async.wait_group 0;" ::: "memory")

__device__ __forceinline__ void ldmx4(uint32_t* r, uint32_t addr) {
    asm volatile("ldmatrix.sync.aligned.m8n8.x4.shared.b16 {%0,%1,%2,%3}, [%4];"
                 : "=r"(r[0]), "=r"(r[1]), "=r"(r[2]), "=r"(r[3]) : "r"(addr));
}
__device__ __forceinline__ void ldmx2(uint32_t* r, uint32_t addr) {
    asm volatile("ldmatrix.sync.aligned.m8n8.x2.shared.b16 {%0,%1}, [%2];"
                 : "=r"(r[0]), "=r"(r[1]) : "r"(addr));
}
__device__ __forceinline__ void mma_fp16(float* d, const uint32_t* a,
                                         const uint32_t* b) {
    asm volatile(
        "mma.sync.aligned.m16n8k16.row.col.f32.f16.f16.f32 "
        "{%0,%1,%2,%3}, {%4,%5,%6,%7}, {%8,%9}, {%0,%1,%2,%3};"
        : "+f"(d[0]), "+f"(d[1]), "+f"(d[2]), "+f"(d[3])
        : "r"(a[0]), "r"(a[1]), "r"(a[2]), "r"(a[3]), "r"(b[0]), "r"(b[1]));
}

// ---------------- kernel 1: zero counters ------------------------------------
__global__ void zero_cnt_kernel() {
    int i = blockIdx.x * blockDim.x + threadIdx.x;
    if (i < N_NODES) g_cnt[i] = 0;
}

// ---------------- kernel 2: bucket edges by destination ----------------------
__global__ void build_buckets_kernel(const int* __restrict__ esrc,
                                     const int* __restrict__ edst,
                                     const int* __restrict__ erel) {
    int i = blockIdx.x * blockDim.x + threadIdx.x;
    if (i >= N_EDGES) return;
    int d   = edst[i];
    int pos = atomicAdd(&g_cnt[d], 1);
    if (pos < CAP) g_bucket[d * CAP + pos] = esrc[i] | (erel[i] << 20);
}

// ---------------- kernel 3: h -> fp16 row image -------------------------------
__global__ void h16conv_kernel(const float* __restrict__ h) {
    int i = blockIdx.x * blockDim.x + threadIdx.x;   // one group of 8 floats
    if (i >= N_NODES * HDIM / 8) return;
    const float4* p = (const float4*)(h + (size_t)i * 8);
    float4 v0 = p[0], v1 = p[1];
    __half2 h0 = __float22half2_rn(make_float2(v0.x, v0.y));
    __half2 h1 = __float22half2_rn(make_float2(v0.z, v0.w));
    __half2 h2 = __float22half2_rn(make_float2(v1.x, v1.y));
    __half2 h3 = __float22half2_rn(make_float2(v1.z, v1.w));
    uint4 o;
    o.x = *(uint32_t*)&h0; o.y = *(uint32_t*)&h1;
    o.z = *(uint32_t*)&h2; o.w = *(uint32_t*)&h3;
    *(uint4*)(g_h16 + (size_t)i * 16) = o;
}

// ---------------- kernel 4: segment reduce (fp16 gather) ----------------------
// One warp per node; lane owns 8 dims (16B). relvectors via 16-bin histogram.
__global__ __launch_bounds__(256)
void reduce_convert_kernel(const float* __restrict__ relv) {
    const int wid  = threadIdx.x >> 5;
    const int lane = threadIdx.x & 31;
    const int node = blockIdx.x * 8 + wid;

    __shared__ int s_ent[8][CAP];
    __shared__ int s_hist[8][16];

    if (lane < 16) s_hist[wid][lane] = 0;
    int cnt = g_cnt[node];
    cnt = cnt < CAP ? cnt : CAP;
    __syncwarp();
    if (lane < cnt) {
        int en = g_bucket[node * CAP + lane];
        s_ent[wid][lane] = en & 0xFFFFF;
        atomicAdd(&s_hist[wid][en >> 20], 1);
    }
    if (lane + 32 < cnt) {
        int en = g_bucket[node * CAP + lane + 32];
        s_ent[wid][lane + 32] = en & 0xFFFFF;
        atomicAdd(&s_hist[wid][en >> 20], 1);
    }
    __syncwarp();

    float a0[8], a1[8];
#pragma unroll
    for (int q = 0; q < 8; q++) { a0[q] = 0.f; a1[q] = 0.f; }

    int e = 0;
    for (; e + 1 < cnt; e += 2) {
        uint4 v0 = *(const uint4*)(g_h16 + (size_t)s_ent[wid][e]     * 512 + lane * 16);
        uint4 v1 = *(const uint4*)(g_h16 + (size_t)s_ent[wid][e + 1] * 512 + lane * 16);
        const __half2* p0 = (const __half2*)&v0;
        const __half2* p1 = (const __half2*)&v1;
#pragma unroll
        for (int q = 0; q < 4; q++) {
            float2 f0 = __half22float2(p0[q]);
            float2 f1 = __half22float2(p1[q]);
            a0[2 * q] += f0.x; a0[2 * q + 1] += f0.y;
            a1[2 * q] += f1.x; a1[2 * q + 1] += f1.y;
        }
    }
    if (e < cnt) {
        uint4 v0 = *(const uint4*)(g_h16 + (size_t)s_ent[wid][e] * 512 + lane * 16);
        const __half2* p0 = (const __half2*)&v0;
#pragma unroll
        for (int q = 0; q < 4; q++) {
            float2 f0 = __half22float2(p0[q]);
            a0[2 * q] += f0.x; a0[2 * q + 1] += f0.y;
        }
    }
    const int j = lane * 8;
#pragma unroll
    for (int r = 0; r < 16; r++) {
        int c = s_hist[wid][r];
        if (c) {
            float cf = (float)c;
            float4 r0 = *(const float4*)&relv[r * HDIM + j];
            float4 r1 = *(const float4*)&relv[r * HDIM + j + 4];
            a1[0] += cf * r0.x; a1[1] += cf * r0.y;
            a1[2] += cf * r0.z; a1[3] += cf * r0.w;
            a1[4] += cf * r1.x; a1[5] += cf * r1.y;
            a1[6] += cf * r1.z; a1[7] += cf * r1.w;
        }
    }
    __half2 o0 = __float22half2_rn(make_float2(a0[0] + a1[0], a0[1] + a1[1]));
    __half2 o1 = __float22half2_rn(make_float2(a0[2] + a1[2], a0[3] + a1[3]));
    __half2 o2 = __float22half2_rn(make_float2(a0[4] + a1[4], a0[5] + a1[5]));
    __half2 o3 = __float22half2_rn(make_float2(a0[6] + a1[6], a0[7] + a1[7]));
    uint4 o;
    o.x = *(uint32_t*)&o0; o.y = *(uint32_t*)&o1;
    o.z = *(uint32_t*)&o2; o.w = *(uint32_t*)&o3;
    *(uint4*)(g_red16 + (size_t)node * 512 + lane * 16) = o;
}

// ---------------- kernel 5: weight fp16 B-image emit --------------------------
// B image per (jt,kc): [2 var][48 rows = gate*16 + jl][32 fp16].
__global__ void wconv_kernel(const float* __restrict__ w_ih,
                             const float* __restrict__ w_hh) {
    int t = blockIdx.x * blockDim.x + threadIdx.x;
    if (t >= JT * KCH * 2 * 48 * 32) return;
    int kl  = t & 31;
    int r2  = t >> 5;
    int row = r2 % 48;  r2 /= 48;
    int var = r2 & 1;   r2 >>= 1;
    int kc  = r2 & 7;
    int jt  = r2 >> 3;
    int gate = row / 16, rl = row % 16;

    const float* W = var ? w_hh : w_ih;
    float v = W[(gate * 256 + jt * 16 + rl) * HDIM + kc * 32 + kl];
    *(__half*)(g_Bimg + (size_t)(jt * KCH + kc) * BC +
               var * 3072 + row * 64 + kl * 2) = __float2half_rn(v);
}

// ---------------- chunk loader ------------------------------------------------
__device__ __forceinline__ void load_chunk(uint32_t sb, int stage,
                                           const uint8_t* redp,
                                           const uint8_t* hp,
                                           const uint8_t* Bb,
                                           int kc, int tid) {
#pragma unroll
    for (int i = 0; i < 4; i++) {           // A: 1024 x 16B
        int idx = tid + i * 256;
        int var = idx >> 9, row = (idx >> 2) & 127, seg = idx & 3;
        const uint8_t* src = (var ? hp : redp) +
                             (size_t)row * 512 + kc * 64 + seg * 16;
        cpasync16(sb + stage * A_STG + var * 10240 + row * 80 + seg * 16, src);
    }
    const uint8_t* Bg = Bb + (size_t)kc * BC;
#pragma unroll
    for (int i = 0; i < 2; i++) {           // B: 384 x 16B
        int idx = tid + i * 256;
        if (idx < 384) {
            int var = idx / 192, rem = idx % 192;
            int row = rem >> 2, seg = rem & 3;
            cpasync16(sb + B_BASE + stage * B_STG + var * 3840 + row * 80 + seg * 16,
                      Bg + var * 3072 + row * 64 + seg * 16);
        }
    }
}

// ---------------- kernel 6: fp16 HMMA dual-GEMM + GRU epilogue ----------------
__global__ __launch_bounds__(256, 3)
void ggnn_mma_kernel(const float* __restrict__ h,
                     const float* __restrict__ b_ih,
                     const float* __restrict__ b_hh,
                     float* __restrict__ out) {
    extern __shared__ __align__(1024) uint8_t sm[];
    const uint32_t sb = smem_u32(sm);
    const int tid   = threadIdx.x;
    const int jtile = blockIdx.x;
    const int mtile = blockIdx.y;
    const int wid   = tid >> 5;
    const int lane  = tid & 31;
    const int lr    = lane >> 2;
    const int lc    = lane & 3;
    const int warp_m = wid & 3;     // 32-row slice
    const int jhalf  = wid >> 2;    // 8-col half of the 16-col j-tile

    const uint8_t* redp = g_red16 + (size_t)mtile * 128 * 512;
    const uint8_t* hp   = g_h16   + (size_t)mtile * 128 * 512;
    const uint8_t* Bb   = g_Bimg  + (size_t)jtile * KCH * BC;

    load_chunk(sb, 0, redp, hp, Bb, 0, tid); CP_COMMIT();
    load_chunk(sb, 1, redp, hp, Bb, 1, tid); CP_COMMIT();

    float acc[2][6][4];   // [mt][g2*3+gate][frag]
#pragma unroll
    for (int a = 0; a < 2; a++)
#pragma unroll
        for (int b = 0; b < 6; b++)
#pragma unroll
            for (int c = 0; c < 4; c++) acc[a][b][c] = 0.0f;

    const int mrow = warp_m * 32;

    for (int c = 0; c < KCH; c++) {
        if (c == KCH - 1) { CP_WAIT0(); } else { CP_WAIT1(); }
        __syncthreads();
        const int s = c & 1;
        const uint32_t abase = sb + s * A_STG +
                               (mrow + (lane & 15)) * 80 + (lane >> 4) * 16;
        const uint32_t bbase = sb + B_BASE + s * B_STG +
                               (jhalf * 8 + (lane & 7)) * 80 + ((lane >> 3) & 1) * 16;

#pragma unroll
        for (int kk = 0; kk < 2; kk++) {
            uint32_t afr[2][2][4];   // [var: 0=red 1=h][mt][frag]
#pragma unroll
            for (int var = 0; var < 2; var++)
#pragma unroll
                for (int mt = 0; mt < 2; mt++)
                    ldmx4(afr[var][mt],
                          abase + var * 10240 + mt * 16 * 80 + kk * 32);
#pragma unroll
            for (int g2 = 0; g2 < 2; g2++)
#pragma unroll
                for (int gate = 0; gate < 3; gate++) {
                    uint32_t bf[2];
                    ldmx2(bf, bbase + g2 * 3840 + gate * 16 * 80 + kk * 32);
                    const int tile = g2 * 3 + gate;
#pragma unroll
                    for (int mt = 0; mt < 2; mt++)
                        mma_fp16(acc[mt][tile], afr[g2][mt], bf);
                }
        }
        __syncthreads();
        if (c + 2 < KCH) {
            load_chunk(sb, s, redp, hp, Bb, c + 2, tid);
            CP_COMMIT();
        }
    }

    // ---- GRU epilogue (register-local) ----
    const int jb = jtile * 16 + jhalf * 8;
    float Bsr[2], Bsz[2], Bin[2], Bhn[2];
#pragma unroll
    for (int cc = 0; cc < 2; cc++) {
        int j = jb + lc * 2 + cc;
        Bsr[cc] = __ldg(&b_ih[j])       + __ldg(&b_hh[j]);
        Bsz[cc] = __ldg(&b_ih[256 + j]) + __ldg(&b_hh[256 + j]);
        Bin[cc] = __ldg(&b_ih[512 + j]);
        Bhn[cc] = __ldg(&b_hh[512 + j]);
    }

#pragma unroll
    for (int mt = 0; mt < 2; mt++)
#pragma unroll
        for (int rr = 0; rr < 2; rr++) {
            int row = mtile * 128 + mrow + mt * 16 + lr + rr * 8;
            if (row >= N_NODES) continue;
            int j0 = jb + lc * 2;
            float2 hv = *(const float2*)&h[(size_t)row * HDIM + j0];
            float o[2];
#pragma unroll
            for (int cc = 0; cc < 2; cc++) {
                int i = rr * 2 + cc;
                float rg = acc[mt][0][i] + acc[mt][3][i] + Bsr[cc];
                float zg = acc[mt][1][i] + acc[mt][4][i] + Bsz[cc];
                float r  = __fdividef(1.0f, 1.0f + __expf(-rg));
                float z  = __fdividef(1.0f, 1.0f + __expf(-zg));
                float ng = acc[mt][2][i] + Bin[cc] +
                           r * (acc[mt][5][i] + Bhn[cc]);
                float ex = __expf(2.0f * ng);
                float n  = 1.0f - __fdividef(2.0f, ex + 1.0f);
                float hvv = (cc == 0) ? hv.x : hv.y;
                o[cc] = (1.0f - z) * n + z * hvv;
            }
            *(float2*)&out[(size_t)row * HDIM + j0] = make_float2(o[0], o[1]);
        }
}

// ---------------- launch --------------------------------------------------------
extern "C" void kernel_launch(void* const* d_in, const int* in_sizes, int n_in,
                              void* d_out, int out_size) {
    const float* h    = (const float*)d_in[0];
    const float* relv = (const float*)d_in[1];
    const float* w_ih = (const float*)d_in[2];
    const float* w_hh = (const float*)d_in[3];
    const float* b_ih = (const float*)d_in[4];
    const float* b_hh = (const float*)d_in[5];
    const int*   esrc = (const int*)d_in[6];
    const int*   edst = (const int*)d_in[7];
    const int*   erel = (const int*)d_in[8];
    float*       out  = (float*)d_out;

    cudaFuncSetAttribute(ggnn_mma_kernel,
                         cudaFuncAttributeMaxDynamicSharedMemorySize, SMEM_TOTAL);

    zero_cnt_kernel<<<(N_NODES + 255) / 256, 256>>>();
    build_buckets_kernel<<<(N_EDGES + 255) / 256, 256>>>(esrc, edst, erel);
    h16conv_kernel<<<(N_NODES * HDIM / 8 + 255) / 256, 256>>>(h);
    wconv_kernel<<<(JT * KCH * 2 * 48 * 32 + 255) / 256, 256>>>(w_ih, w_hh);
    reduce_convert_kernel<<<N_NODES / 8, 256>>>(relv);

    dim3 grid(JT, MT);
    ggnn_mma_kernel<<<grid, 256, SMEM_TOTAL>>>(h, b_ih, b_hh, out);
}